// round 1
// baseline (speedup 1.0000x reference)
#include <cuda_runtime.h>
#include <cstdint>

// Problem constants
#define NPIX   1048576      // 16 * 256 * 256
#define HW     65536        // 256*256
#define TPB    256

typedef unsigned long long ull;

__device__ __forceinline__ ull ffma2(ull a, ull b, ull c) {
    ull d;
    asm("fma.rn.f32x2 %0, %1, %2, %3;" : "=l"(d) : "l"(a), "l"(b), "l"(c));
    return d;
}
__device__ __forceinline__ ull pk(float lo, float hi) {
    ull r;
    asm("mov.b64 %0, {%1, %2};" : "=l"(r) : "f"(lo), "f"(hi));
    return r;
}
__device__ __forceinline__ float2 upk(ull v) {
    float2 r;
    asm("mov.b64 {%0, %1}, %2;" : "=f"(r.x), "=f"(r.y) : "l"(v));
    return r;
}

struct SmemW {
    ulonglong2 kw[64][8];   // [c][j] -> packed output pairs (2j*2.. ) : 8KB
    ulonglong2 vw[64][8];
    ulonglong2 qw[64][8];
    ulonglong2 d1[32][4];   // d1_w [16,32] packed over outputs
    ulonglong2 d2[16][2];   // d2_w [8,16]
    ulonglong2 d3[8][4];    // d3_w [16,8]
    ull kb[16], vb[16], qb[16], d3b[8];
};

__global__ __launch_bounds__(TPB)
void fused_att_mlp_kernel(const float* __restrict__ kv_in,
                          const float* __restrict__ q_in,
                          const float* __restrict__ key_w,  const float* __restrict__ key_b,
                          const float* __restrict__ value_w,const float* __restrict__ value_b,
                          const float* __restrict__ query_w,const float* __restrict__ query_b,
                          const float* __restrict__ scale,
                          const float* __restrict__ d1_w,
                          const float* __restrict__ d2_w,
                          const float* __restrict__ d3_w,  const float* __restrict__ d3_b,
                          float* __restrict__ out)
{
    __shared__ SmemW s;
    const int tid = threadIdx.x;

    // ---- cooperative weight packing into shared ----
    {
        ull* kwf = (ull*)s.kw;
        ull* vwf = (ull*)s.vw;
        ull* qwf = (ull*)s.qw;
        for (int i = tid; i < 1024; i += TPB) {
            int c = i >> 4, p = i & 15;                // w[o][c], o = 2p, 2p+1 ; stride 64
            kwf[i] = pk(key_w  [p*128 + c], key_w  [p*128 + 64 + c]);
            vwf[i] = pk(value_w[p*128 + c], value_w[p*128 + 64 + c]);
            qwf[i] = pk(query_w[p*128 + c], query_w[p*128 + 64 + c]);
        }
        ull* d1f = (ull*)s.d1;
        for (int i = tid; i < 256; i += TPB) {
            int c = i >> 3, p = i & 7;                 // d1_w [16,32]: stride 32
            d1f[i] = pk(d1_w[p*64 + c], d1_w[p*64 + 32 + c]);
        }
        if (tid < 64) {
            int c = tid >> 2, p = tid & 3;             // d2_w [8,16]: stride 16
            ((ull*)s.d2)[tid] = pk(d2_w[p*32 + c], d2_w[p*32 + 16 + c]);
        }
        if (tid >= 64 && tid < 128) {
            int i = tid - 64;
            int c = i >> 3, p = i & 7;                 // d3_w [16,8]: stride 8
            ((ull*)s.d3)[i] = pk(d3_w[p*16 + c], d3_w[p*16 + 8 + c]);
        }
        if (tid >= 128 && tid < 144) {
            int p = tid - 128;
            s.kb[p] = pk(key_b  [2*p], key_b  [2*p+1]);
            s.vb[p] = pk(value_b[2*p], value_b[2*p+1]);
            s.qb[p] = pk(query_b[2*p], query_b[2*p+1]);
        }
        if (tid >= 144 && tid < 152) {
            int p = tid - 144;
            s.d3b[p] = pk(d3_b[2*p], d3_b[2*p+1]);
        }
    }
    __syncthreads();

    const int g = blockIdx.x * TPB + tid;
    if (g >= NPIX) return;
    const int b   = g >> 16;       // batch
    const int pix = g & (HW - 1);  // pixel within batch

    const float* kvp = kv_in + ((size_t)b << 22) + pix;   // b*64*65536
    const float* qp  = q_in  + ((size_t)b << 22) + pix;

    // ---- three 1x1 convs, packed f32x2 accumulators (bias-initialized) ----
    ull ka[16], va[16], qa[16];
    #pragma unroll
    for (int p = 0; p < 16; p++) { ka[p] = s.kb[p]; va[p] = s.vb[p]; qa[p] = s.qb[p]; }

    #pragma unroll 4
    for (int c = 0; c < 64; c++) {
        const float xk = __ldg(kvp + ((size_t)c << 16));
        const float xq = __ldg(qp  + ((size_t)c << 16));
        const ull xk2 = pk(xk, xk);
        const ull xq2 = pk(xq, xq);
        #pragma unroll
        for (int j = 0; j < 8; j++) {
            ulonglong2 w;
            w = s.kw[c][j];
            ka[2*j]   = ffma2(w.x, xk2, ka[2*j]);
            ka[2*j+1] = ffma2(w.y, xk2, ka[2*j+1]);
            w = s.vw[c][j];
            va[2*j]   = ffma2(w.x, xk2, va[2*j]);
            va[2*j+1] = ffma2(w.y, xk2, va[2*j+1]);
            w = s.qw[c][j];
            qa[2*j]   = ffma2(w.x, xq2, qa[2*j]);
            qa[2*j+1] = ffma2(w.y, xq2, qa[2*j+1]);
        }
    }

    // ---- sigmoid gate + value ----
    const float sc = __ldg(scale);
    float xv[32];
    #pragma unroll
    for (int p = 0; p < 16; p++) {
        float2 kf = upk(ka[p]);
        float2 qf = upk(qa[p]);
        float2 vf = upk(va[p]);
        float t0 = kf.x * qf.x * sc;
        float t1 = kf.y * qf.y * sc;
        float a0 = __fdividef(1.0f, 1.0f + __expf(-t0));
        float a1 = __fdividef(1.0f, 1.0f + __expf(-t1));
        xv[2*p]   = a0 * vf.x;
        xv[2*p+1] = a1 * vf.y;
    }

    // ---- d1: 32 -> 16, relu ----
    ull h1[8];
    #pragma unroll
    for (int j = 0; j < 8; j++) h1[j] = 0ull;
    #pragma unroll
    for (int c = 0; c < 32; c++) {
        const ull xc = pk(xv[c], xv[c]);
        #pragma unroll
        for (int j = 0; j < 4; j++) {
            ulonglong2 w = s.d1[c][j];
            h1[2*j]   = ffma2(w.x, xc, h1[2*j]);
            h1[2*j+1] = ffma2(w.y, xc, h1[2*j+1]);
        }
    }
    float r1[16];
    #pragma unroll
    for (int j = 0; j < 8; j++) {
        float2 f = upk(h1[j]);
        r1[2*j]   = fmaxf(f.x, 0.0f);
        r1[2*j+1] = fmaxf(f.y, 0.0f);
    }

    // ---- d2: 16 -> 8, relu ----
    ull h2[4];
    #pragma unroll
    for (int j = 0; j < 4; j++) h2[j] = 0ull;
    #pragma unroll
    for (int c = 0; c < 16; c++) {
        const ull xc = pk(r1[c], r1[c]);
        #pragma unroll
        for (int j = 0; j < 2; j++) {
            ulonglong2 w = s.d2[c][j];
            h2[2*j]   = ffma2(w.x, xc, h2[2*j]);
            h2[2*j+1] = ffma2(w.y, xc, h2[2*j+1]);
        }
    }
    float r2[8];
    #pragma unroll
    for (int j = 0; j < 4; j++) {
        float2 f = upk(h2[j]);
        r2[2*j]   = fmaxf(f.x, 0.0f);
        r2[2*j+1] = fmaxf(f.y, 0.0f);
    }

    // ---- d3: 8 -> 16 (+bias) ----
    ull h3[8];
    #pragma unroll
    for (int j = 0; j < 8; j++) h3[j] = s.d3b[j];
    #pragma unroll
    for (int c = 0; c < 8; c++) {
        const ull xc = pk(r2[c], r2[c]);
        #pragma unroll
        for (int j = 0; j < 4; j++) {
            ulonglong2 w = s.d3[c][j];
            h3[2*j]   = ffma2(w.x, xc, h3[2*j]);
            h3[2*j+1] = ffma2(w.y, xc, h3[2*j+1]);
        }
    }

    // ---- store [16,16,256,256] ----
    float* op = out + ((size_t)b << 20) + pix;   // b*16*65536
    #pragma unroll
    for (int j = 0; j < 8; j++) {
        float2 f = upk(h3[j]);
        op[(size_t)(2*j)     << 16] = f.x;
        op[(size_t)(2*j + 1) << 16] = f.y;
    }
}

extern "C" void kernel_launch(void* const* d_in, const int* in_sizes, int n_in,
                              void* d_out, int out_size)
{
    const float* kv_in   = (const float*)d_in[0];
    const float* q_in    = (const float*)d_in[1];
    const float* key_w   = (const float*)d_in[2];
    const float* key_b   = (const float*)d_in[3];
    const float* value_w = (const float*)d_in[4];
    const float* value_b = (const float*)d_in[5];
    const float* query_w = (const float*)d_in[6];
    const float* query_b = (const float*)d_in[7];
    const float* scale   = (const float*)d_in[8];
    const float* d1_w    = (const float*)d_in[9];
    const float* d2_w    = (const float*)d_in[10];
    const float* d3_w    = (const float*)d_in[11];
    const float* d3_b    = (const float*)d_in[12];
    float* out = (float*)d_out;

    const int grid = (NPIX + TPB - 1) / TPB;
    fused_att_mlp_kernel<<<grid, TPB>>>(kv_in, q_in, key_w, key_b, value_w, value_b,
                                        query_w, query_b, scale, d1_w, d2_w, d3_w, d3_b,
                                        out);
}

// round 2
// speedup vs baseline: 1.8836x; 1.8836x over previous
#include <cuda_runtime.h>
#include <cstdint>

#define TPB    256
#define PITCH  132   // floats per channel row in activation smem
#define WP     65    // padded pitch for 64-wide weight rows

__device__ __forceinline__ uint32_t to_tf32(float f) {
    uint32_t r; asm("cvt.rna.tf32.f32 %0, %1;" : "=r"(r) : "f"(f)); return r;
}
__device__ __forceinline__ void mma8(float& c0, float& c1, float& c2, float& c3,
                                     uint32_t a0, uint32_t a1, uint32_t a2, uint32_t a3,
                                     uint32_t b0, uint32_t b1) {
    asm volatile("mma.sync.aligned.m16n8k8.row.col.f32.tf32.tf32.f32 "
                 "{%0,%1,%2,%3},{%4,%5,%6,%7},{%8,%9},{%0,%1,%2,%3};"
                 : "+f"(c0), "+f"(c1), "+f"(c2), "+f"(c3)
                 : "r"(a0), "r"(a1), "r"(a2), "r"(a3), "r"(b0), "r"(b1));
}

__global__ __launch_bounds__(TPB, 2)
void fused_tc_kernel(const float* __restrict__ kv_in, const float* __restrict__ q_in,
                     const float* __restrict__ key_w,   const float* __restrict__ key_b,
                     const float* __restrict__ value_w, const float* __restrict__ value_b,
                     const float* __restrict__ query_w, const float* __restrict__ query_b,
                     const float* __restrict__ scale,
                     const float* __restrict__ d1_w, const float* __restrict__ d2_w,
                     const float* __restrict__ d3_w, const float* __restrict__ d3_b,
                     float* __restrict__ out)
{
    extern __shared__ char smraw[];
    float*    smKV = (float*)smraw;                  // [64][PITCH] fp32
    float*    smQ  = smKV + 64 * PITCH;              // [64][PITCH] fp32 (later: exchange buf)
    uint32_t* xb   = (uint32_t*)smQ;                 // tf32 view of exchange buffer
    uint32_t* wKV  = (uint32_t*)(smQ + 64 * PITCH);  // [64][WP]  rows 0-31 key, 32-63 value
    uint32_t* wQm  = wKV + 64 * WP;                  // [32][WP]
    uint32_t* wD1  = wQm + 32 * WP;                  // [16][33]
    uint32_t* wD2  = wD1 + 16 * 33;                  // [8][17]
    uint32_t* wD3  = wD2 + 8 * 17;                   // [16][9]
    float*    bia  = (float*)(wD3 + 16 * 9);         // kb[0:32] vb[32:64] qb[64:96] d3b[96:112] scale[112]

    const int tid = threadIdx.x;

    // ---- weights -> smem (pre-converted to tf32) ----
    for (int i = tid; i < 2048; i += TPB) {
        int o = i >> 6, c = i & 63;
        wKV[o * WP + c]        = to_tf32(key_w[i]);
        wKV[(o + 32) * WP + c] = to_tf32(value_w[i]);
        wQm[o * WP + c]        = to_tf32(query_w[i]);
    }
    for (int i = tid; i < 512; i += TPB) wD1[(i >> 5) * 33 + (i & 31)] = to_tf32(d1_w[i]);
    if (tid < 128) wD2[(tid >> 4) * 17 + (tid & 15)] = to_tf32(d2_w[tid]);
    if (tid < 128) wD3[(tid >> 3) * 9  + (tid & 7) ] = to_tf32(d3_w[tid]);
    if (tid < 32) { bia[tid] = key_b[tid]; bia[32 + tid] = value_b[tid]; bia[64 + tid] = query_b[tid]; }
    if (tid >= 32 && tid < 48) bia[96 + tid - 32] = d3_b[tid - 32];
    if (tid == 48) bia[112] = scale[0];

    // ---- input tiles -> smem (channel-major, coalesced float4) ----
    const int pg0 = blockIdx.x << 7;     // 128 pixels per block, never crosses batch
    const int bb  = pg0 >> 16;
    const int px0 = pg0 & 65535;
    const float* kvb = kv_in + ((size_t)bb << 22) + px0;
    const float* qpb = q_in  + ((size_t)bb << 22) + px0;
    for (int i = tid; i < 2048; i += TPB) {
        int c = i >> 5, p = i & 31;
        float4 a = *(const float4*)(kvb + ((size_t)c << 16) + 4 * p);
        float4 b = *(const float4*)(qpb + ((size_t)c << 16) + 4 * p);
        *(float4*)&smKV[c * PITCH + 4 * p] = a;
        *(float4*)&smQ [c * PITCH + 4 * p] = b;
    }
    __syncthreads();

    const int warp = tid >> 5, lane = tid & 31;
    const int g = lane >> 2, tg = lane & 3;
    const int col0 = warp * 16 + g;      // this thread's pixel column (rows g / g+8)

    // C fragments: [0..7] = kv GEMM (k: tiles 0-3, v: tiles 4-7), [8..11] = q GEMM.
    // Bias folded into accumulator init (cols 2tg,2tg+1 within 8-wide tile j).
    float C[12][4];
    #pragma unroll
    for (int j = 0; j < 8; j++) {
        float b0 = bia[8 * j + 2 * tg], b1 = bia[8 * j + 2 * tg + 1];
        C[j][0] = b0; C[j][1] = b1; C[j][2] = b0; C[j][3] = b1;
    }
    #pragma unroll
    for (int j = 0; j < 4; j++) {
        float b0 = bia[64 + 8 * j + 2 * tg], b1 = bia[64 + 8 * j + 2 * tg + 1];
        C[8 + j][0] = b0; C[8 + j][1] = b1; C[8 + j][2] = b0; C[8 + j][3] = b1;
    }

    // ---- conv GEMMs: K = 64 in 8 steps ----
    #pragma unroll
    for (int kb = 0; kb < 64; kb += 8) {
        uint32_t a0 = to_tf32(smKV[(kb + tg    ) * PITCH + col0    ]);
        uint32_t a1 = to_tf32(smKV[(kb + tg    ) * PITCH + col0 + 8]);
        uint32_t a2 = to_tf32(smKV[(kb + tg + 4) * PITCH + col0    ]);
        uint32_t a3 = to_tf32(smKV[(kb + tg + 4) * PITCH + col0 + 8]);
        #pragma unroll
        for (int j = 0; j < 8; j++) {
            uint32_t b0 = wKV[(8 * j + g) * WP + kb + tg];
            uint32_t b1 = wKV[(8 * j + g) * WP + kb + tg + 4];
            mma8(C[j][0], C[j][1], C[j][2], C[j][3], a0, a1, a2, a3, b0, b1);
        }
        uint32_t q0 = to_tf32(smQ[(kb + tg    ) * PITCH + col0    ]);
        uint32_t q1 = to_tf32(smQ[(kb + tg    ) * PITCH + col0 + 8]);
        uint32_t q2 = to_tf32(smQ[(kb + tg + 4) * PITCH + col0    ]);
        uint32_t q3 = to_tf32(smQ[(kb + tg + 4) * PITCH + col0 + 8]);
        #pragma unroll
        for (int j = 0; j < 4; j++) {
            uint32_t b0 = wQm[(8 * j + g) * WP + kb + tg];
            uint32_t b1 = wQm[(8 * j + g) * WP + kb + tg + 4];
            mma8(C[8 + j][0], C[8 + j][1], C[8 + j][2], C[8 + j][3], q0, q1, q2, q3, b0, b1);
        }
    }

    // ---- gating: x = sigmoid(k*q*scale) * v  (k,q,v aligned per thread/reg) ----
    const float sc = bia[112];
    __syncwarp();
    #pragma unroll
    for (int j = 0; j < 4; j++) {
        #pragma unroll
        for (int e = 0; e < 4; e++) {
            float t = C[j][e] * C[8 + j][e] * sc;
            float s = 1.0f / (1.0f + __expf(-t));
            float x = s * C[4 + j][e];
            int c = 8 * j + 2 * tg + (e & 1);
            int p = warp * 16 + g + ((e >> 1) << 3);
            xb[c * PITCH + p] = to_tf32(x);      // warp-private columns of old q buffer
        }
    }
    __syncwarp();

    // ---- d1: 32 -> 16 (relu) ----
    float D1[2][4] = {};
    #pragma unroll
    for (int kb = 0; kb < 32; kb += 8) {
        uint32_t a0 = xb[(kb + tg    ) * PITCH + col0    ];
        uint32_t a1 = xb[(kb + tg    ) * PITCH + col0 + 8];
        uint32_t a2 = xb[(kb + tg + 4) * PITCH + col0    ];
        uint32_t a3 = xb[(kb + tg + 4) * PITCH + col0 + 8];
        #pragma unroll
        for (int j = 0; j < 2; j++) {
            uint32_t b0 = wD1[(8 * j + g) * 33 + kb + tg];
            uint32_t b1 = wD1[(8 * j + g) * 33 + kb + tg + 4];
            mma8(D1[j][0], D1[j][1], D1[j][2], D1[j][3], a0, a1, a2, a3, b0, b1);
        }
    }
    __syncwarp();
    #pragma unroll
    for (int j = 0; j < 2; j++)
        #pragma unroll
        for (int e = 0; e < 4; e++) {
            int c = 8 * j + 2 * tg + (e & 1);
            int p = warp * 16 + g + ((e >> 1) << 3);
            xb[c * PITCH + p] = to_tf32(fmaxf(D1[j][e], 0.0f));
        }
    __syncwarp();

    // ---- d2: 16 -> 8 (relu) ----
    float D2[4] = {};
    #pragma unroll
    for (int kb = 0; kb < 16; kb += 8) {
        uint32_t a0 = xb[(kb + tg    ) * PITCH + col0    ];
        uint32_t a1 = xb[(kb + tg    ) * PITCH + col0 + 8];
        uint32_t a2 = xb[(kb + tg + 4) * PITCH + col0    ];
        uint32_t a3 = xb[(kb + tg + 4) * PITCH + col0 + 8];
        uint32_t b0 = wD2[g * 17 + kb + tg];
        uint32_t b1 = wD2[g * 17 + kb + tg + 4];
        mma8(D2[0], D2[1], D2[2], D2[3], a0, a1, a2, a3, b0, b1);
    }
    __syncwarp();
    #pragma unroll
    for (int e = 0; e < 4; e++) {
        int c = 2 * tg + (e & 1);
        int p = warp * 16 + g + ((e >> 1) << 3);
        xb[c * PITCH + p] = to_tf32(fmaxf(D2[e], 0.0f));
    }
    __syncwarp();

    // ---- d3: 8 -> 16 (+bias) ----
    float D3[2][4];
    #pragma unroll
    for (int j = 0; j < 2; j++) {
        float b0 = bia[96 + 8 * j + 2 * tg], b1 = bia[96 + 8 * j + 2 * tg + 1];
        D3[j][0] = b0; D3[j][1] = b1; D3[j][2] = b0; D3[j][3] = b1;
    }
    {
        uint32_t a0 = xb[(tg    ) * PITCH + col0    ];
        uint32_t a1 = xb[(tg    ) * PITCH + col0 + 8];
        uint32_t a2 = xb[(tg + 4) * PITCH + col0    ];
        uint32_t a3 = xb[(tg + 4) * PITCH + col0 + 8];
        #pragma unroll
        for (int j = 0; j < 2; j++) {
            uint32_t b0 = wD3[(8 * j + g) * 9 + tg];
            uint32_t b1 = wD3[(8 * j + g) * 9 + tg + 4];
            mma8(D3[j][0], D3[j][1], D3[j][2], D3[j][3], a0, a1, a2, a3, b0, b1);
        }
    }

    // ---- store [16 out-ch][pixels] ----
    const int pixg = px0 + warp * 16 + g;
    #pragma unroll
    for (int j = 0; j < 2; j++)
        #pragma unroll
        for (int e = 0; e < 4; e++) {
            int ch = 8 * j + 2 * tg + (e & 1);
            int pp = pixg + ((e >> 1) << 3);
            out[(((size_t)(bb * 16 + ch)) << 16) + pp] = D3[j][e];
        }
}

extern "C" void kernel_launch(void* const* d_in, const int* in_sizes, int n_in,
                              void* d_out, int out_size)
{
    const float* kv_in   = (const float*)d_in[0];
    const float* q_in    = (const float*)d_in[1];
    const float* key_w   = (const float*)d_in[2];
    const float* key_b   = (const float*)d_in[3];
    const float* value_w = (const float*)d_in[4];
    const float* value_b = (const float*)d_in[5];
    const float* query_w = (const float*)d_in[6];
    const float* query_b = (const float*)d_in[7];
    const float* scale   = (const float*)d_in[8];
    const float* d1_w    = (const float*)d_in[9];
    const float* d2_w    = (const float*)d_in[10];
    const float* d3_w    = (const float*)d_in[11];
    const float* d3_b    = (const float*)d_in[12];
    float* out = (float*)d_out;

    const int SMEM = (64 * PITCH * 2) * 4
                   + (64 * WP + 32 * WP + 16 * 33 + 8 * 17 + 16 * 9) * 4
                   + 113 * 4;   // = 96228 bytes
    cudaFuncSetAttribute(fused_tc_kernel, cudaFuncAttributeMaxDynamicSharedMemorySize, SMEM);

    fused_tc_kernel<<<8192, TPB, SMEM>>>(kv_in, q_in, key_w, key_b, value_w, value_b,
                                         query_w, query_b, scale, d1_w, d2_w, d3_w, d3_b,
                                         out);
}

// round 5
// speedup vs baseline: 2.7565x; 1.4634x over previous
#include <cuda_runtime.h>
#include <cstdint>

#define TPB    256
#define PITCH  136   // activation pitch in 32-bit words; 136 % 32 == 8 -> conflict-free

__device__ __forceinline__ uint32_t to_tf32(float f) {
    uint32_t r; asm("cvt.rna.tf32.f32 %0, %1;" : "=r"(r) : "f"(f)); return r;
}
__device__ __forceinline__ void mma8(float& c0, float& c1, float& c2, float& c3,
                                     uint32_t a0, uint32_t a1, uint32_t a2, uint32_t a3,
                                     uint32_t b0, uint32_t b1) {
    asm volatile("mma.sync.aligned.m16n8k8.row.col.f32.tf32.tf32.f32 "
                 "{%0,%1,%2,%3},{%4,%5,%6,%7},{%8,%9},{%0,%1,%2,%3};"
                 : "+f"(c0), "+f"(c1), "+f"(c2), "+f"(c3)
                 : "r"(a0), "r"(a1), "r"(a2), "r"(a3), "r"(b0), "r"(b1));
}
// Pack weight column c into pair-slot: (w[8s+tg], w[8s+tg+4]) adjacent -> LDS.64
__device__ __forceinline__ int wslot(int c) {
    return ((c >> 3) << 3) + ((c & 3) << 1) + ((c >> 2) & 1);
}

// smem word layout
#define OFF_KV   0
#define OFF_Q    (64 * PITCH)
#define OFF_WKV  (2 * 64 * PITCH)          // [64][72]  rows 0-31 key, 32-63 value
#define OFF_WQ   (OFF_WKV + 64 * 72)       // [32][72]
#define OFF_WD1  (OFF_WQ  + 32 * 72)       // [16][40]
#define OFF_WD2  (OFF_WD1 + 16 * 40)       // [8][24]
#define OFF_WD3  (OFF_WD2 + 8 * 24)        // [16][8]
#define OFF_BIA  (OFF_WD3 + 16 * 8)        // float[113]
#define SMEM_WORDS (OFF_BIA + 113)

__global__ __launch_bounds__(TPB, 2)
void fused_tc2_kernel(const float* __restrict__ kv_in, const float* __restrict__ q_in,
                      const float* __restrict__ key_w,   const float* __restrict__ key_b,
                      const float* __restrict__ value_w, const float* __restrict__ value_b,
                      const float* __restrict__ query_w, const float* __restrict__ query_b,
                      const float* __restrict__ scale,
                      const float* __restrict__ d1_w, const float* __restrict__ d2_w,
                      const float* __restrict__ d3_w, const float* __restrict__ d3_b,
                      float* __restrict__ out)
{
    extern __shared__ uint32_t sm[];
    uint32_t* smKV = sm + OFF_KV;     // tf32 [64][PITCH]
    uint32_t* smQ  = sm + OFF_Q;      // tf32 [64][PITCH] (reused as MLP exchange)
    uint32_t* wKVp = sm + OFF_WKV;
    uint32_t* wQp  = sm + OFF_WQ;
    uint32_t* wD1p = sm + OFF_WD1;
    uint32_t* wD2p = sm + OFF_WD2;
    uint32_t* wD3p = sm + OFF_WD3;
    float*    bia  = (float*)(sm + OFF_BIA);

    const int tid = threadIdx.x;

    // ---- weights -> smem, tf32, pair-packed ----
    for (int i = tid; i < 2048; i += TPB) {
        int o = i >> 6, s = wslot(i & 63);
        wKVp[o * 72 + s]        = to_tf32(key_w[i]);
        wKVp[(o + 32) * 72 + s] = to_tf32(value_w[i]);
        wQp[o * 72 + s]         = to_tf32(query_w[i]);
    }
    for (int i = tid; i < 512; i += TPB) wD1p[(i >> 5) * 40 + wslot(i & 31)] = to_tf32(d1_w[i]);
    if (tid < 128) wD2p[(tid >> 4) * 24 + wslot(tid & 15)] = to_tf32(d2_w[tid]);
    if (tid < 128) wD3p[(tid >> 3) * 8  + wslot(tid & 7) ] = to_tf32(d3_w[tid]);
    if (tid < 32) { bia[tid] = key_b[tid]; bia[32 + tid] = value_b[tid]; bia[64 + tid] = query_b[tid]; }
    if (tid >= 32 && tid < 48) bia[96 + tid - 32] = d3_b[tid - 32];
    if (tid == 48) bia[112] = scale[0];

    // ---- input tiles -> smem, converted to tf32 at load time ----
    const int pg0 = blockIdx.x << 7;
    const int bb  = pg0 >> 16;
    const int px0 = pg0 & 65535;
    const float* kvb = kv_in + ((size_t)bb << 22) + px0;
    const float* qpb = q_in  + ((size_t)bb << 22) + px0;
    for (int i = tid; i < 2048; i += TPB) {
        int c = i >> 5, p = i & 31;
        float4 a = *(const float4*)(kvb + ((size_t)c << 16) + 4 * p);
        float4 b = *(const float4*)(qpb + ((size_t)c << 16) + 4 * p);
        uint4 ua = make_uint4(to_tf32(a.x), to_tf32(a.y), to_tf32(a.z), to_tf32(a.w));
        uint4 ub = make_uint4(to_tf32(b.x), to_tf32(b.y), to_tf32(b.z), to_tf32(b.w));
        *(uint4*)&smKV[c * PITCH + 4 * p] = ua;
        *(uint4*)&smQ [c * PITCH + 4 * p] = ub;
    }
    __syncthreads();

    const int warp = tid >> 5, lane = tid & 31;
    const int g = lane >> 2, tg = lane & 3;
    const int col0 = warp * 16 + g;

    // C fragments: [0..3]=k, [4..7]=v, [8..11]=q. Bias folded into init.
    float C[12][4];
    #pragma unroll
    for (int j = 0; j < 8; j++) {
        float b0 = bia[8 * j + 2 * tg], b1 = bia[8 * j + 2 * tg + 1];
        C[j][0] = b0; C[j][1] = b1; C[j][2] = b0; C[j][3] = b1;
    }
    #pragma unroll
    for (int j = 0; j < 4; j++) {
        float b0 = bia[64 + 8 * j + 2 * tg], b1 = bia[64 + 8 * j + 2 * tg + 1];
        C[8 + j][0] = b0; C[8 + j][1] = b1; C[8 + j][2] = b0; C[8 + j][3] = b1;
    }

    // ---- conv GEMMs: K = 64 in 8 steps ----
    #pragma unroll
    for (int s = 0; s < 8; s++) {
        const int kb = s * 8;
        uint32_t a0 = smKV[(kb + tg    ) * PITCH + col0    ];
        uint32_t a1 = smKV[(kb + tg    ) * PITCH + col0 + 8];
        uint32_t a2 = smKV[(kb + tg + 4) * PITCH + col0    ];
        uint32_t a3 = smKV[(kb + tg + 4) * PITCH + col0 + 8];
        #pragma unroll
        for (int j = 0; j < 8; j++) {
            uint2 b = *(const uint2*)&wKVp[(8 * j + g) * 72 + kb + 2 * tg];
            mma8(C[j][0], C[j][1], C[j][2], C[j][3], a0, a1, a2, a3, b.x, b.y);
        }
        uint32_t q0 = smQ[(kb + tg    ) * PITCH + col0    ];
        uint32_t q1 = smQ[(kb + tg    ) * PITCH + col0 + 8];
        uint32_t q2 = smQ[(kb + tg + 4) * PITCH + col0    ];
        uint32_t q3 = smQ[(kb + tg + 4) * PITCH + col0 + 8];
        #pragma unroll
        for (int j = 0; j < 4; j++) {
            uint2 b = *(const uint2*)&wQp[(8 * j + g) * 72 + kb + 2 * tg];
            mma8(C[8 + j][0], C[8 + j][1], C[8 + j][2], C[8 + j][3], q0, q1, q2, q3, b.x, b.y);
        }
    }

    // ---- gating: x = sigmoid(k*q*scale) * v  (warp-private columns of smQ) ----
    const float sc = bia[112];
    uint32_t* xb = smQ;
    __syncwarp();
    #pragma unroll
    for (int j = 0; j < 4; j++) {
        #pragma unroll
        for (int e = 0; e < 4; e++) {
            float t = C[j][e] * C[8 + j][e] * sc;
            float sg = 1.0f / (1.0f + __expf(-t));
            float x = sg * C[4 + j][e];
            int c = 8 * j + 2 * tg + (e & 1);
            int p = warp * 16 + g + ((e >> 1) << 3);
            xb[c * PITCH + p] = to_tf32(x);
        }
    }
    __syncwarp();

    // ---- d1: 32 -> 16 (relu) ----
    float D1[2][4] = {};
    #pragma unroll
    for (int s = 0; s < 4; s++) {
        const int kb = s * 8;
        uint32_t a0 = xb[(kb + tg    ) * PITCH + col0    ];
        uint32_t a1 = xb[(kb + tg    ) * PITCH + col0 + 8];
        uint32_t a2 = xb[(kb + tg + 4) * PITCH + col0    ];
        uint32_t a3 = xb[(kb + tg + 4) * PITCH + col0 + 8];
        #pragma unroll
        for (int j = 0; j < 2; j++) {
            uint2 b = *(const uint2*)&wD1p[(8 * j + g) * 40 + kb + 2 * tg];
            mma8(D1[j][0], D1[j][1], D1[j][2], D1[j][3], a0, a1, a2, a3, b.x, b.y);
        }
    }
    __syncwarp();
    #pragma unroll
    for (int j = 0; j < 2; j++)
        #pragma unroll
        for (int e = 0; e < 4; e++) {
            int c = 8 * j + 2 * tg + (e & 1);
            int p = warp * 16 + g + ((e >> 1) << 3);
            xb[c * PITCH + p] = to_tf32(fmaxf(D1[j][e], 0.0f));
        }
    __syncwarp();

    // ---- d2: 16 -> 8 (relu) ----
    float D2[4] = {};
    #pragma unroll
    for (int s = 0; s < 2; s++) {
        const int kb = s * 8;
        uint32_t a0 = xb[(kb + tg    ) * PITCH + col0    ];
        uint32_t a1 = xb[(kb + tg    ) * PITCH + col0 + 8];
        uint32_t a2 = xb[(kb + tg + 4) * PITCH + col0    ];
        uint32_t a3 = xb[(kb + tg + 4) * PITCH + col0 + 8];
        uint2 b = *(const uint2*)&wD2p[g * 24 + kb + 2 * tg];
        mma8(D2[0], D2[1], D2[2], D2[3], a0, a1, a2, a3, b.x, b.y);
    }
    __syncwarp();
    #pragma unroll
    for (int e = 0; e < 4; e++) {
        int c = 2 * tg + (e & 1);
        int p = warp * 16 + g + ((e >> 1) << 3);
        xb[c * PITCH + p] = to_tf32(fmaxf(D2[e], 0.0f));
    }
    __syncwarp();

    // ---- d3: 8 -> 16 (+bias) ----
    float D3[2][4];
    #pragma unroll
    for (int j = 0; j < 2; j++) {
        float b0 = bia[96 + 8 * j + 2 * tg], b1 = bia[96 + 8 * j + 2 * tg + 1];
        D3[j][0] = b0; D3[j][1] = b1; D3[j][2] = b0; D3[j][3] = b1;
    }
    {
        uint32_t a0 = xb[(tg    ) * PITCH + col0    ];
        uint32_t a1 = xb[(tg    ) * PITCH + col0 + 8];
        uint32_t a2 = xb[(tg + 4) * PITCH + col0    ];
        uint32_t a3 = xb[(tg + 4) * PITCH + col0 + 8];
        #pragma unroll
        for (int j = 0; j < 2; j++) {
            uint2 b = *(const uint2*)&wD3p[(8 * j + g) * 8 + 2 * tg];
            mma8(D3[j][0], D3[j][1], D3[j][2], D3[j][3], a0, a1, a2, a3, b.x, b.y);
        }
    }

    // ---- store ----
    const int pixg = px0 + warp * 16 + g;
    #pragma unroll
    for (int j = 0; j < 2; j++)
        #pragma unroll
        for (int e = 0; e < 4; e++) {
            int ch = 8 * j + 2 * tg + (e & 1);
            int pp = pixg + ((e >> 1) << 3);
            out[(((size_t)(bb * 16 + ch)) << 16) + pp] = D3[j][e];
        }
}

extern "C" void kernel_launch(void* const* d_in, const int* in_sizes, int n_in,
                              void* d_out, int out_size)
{
    const float* kv_in   = (const float*)d_in[0];
    const float* q_in    = (const float*)d_in[1];
    const float* key_w   = (const float*)d_in[2];
    const float* key_b   = (const float*)d_in[3];
    const float* value_w = (const float*)d_in[4];
    const float* value_b = (const float*)d_in[5];
    const float* query_w = (const float*)d_in[6];
    const float* query_b = (const float*)d_in[7];
    const float* scale   = (const float*)d_in[8];
    const float* d1_w    = (const float*)d_in[9];
    const float* d2_w    = (const float*)d_in[10];
    const float* d3_w    = (const float*)d_in[11];
    const float* d3_b    = (const float*)d_in[12];
    float* out = (float*)d_out;

    const int SMEM = SMEM_WORDS * 4;   // 101572 bytes
    static int configured = 0;
    if (!configured) {
        cudaFuncSetAttribute(fused_tc2_kernel, cudaFuncAttributeMaxDynamicSharedMemorySize, SMEM);
        configured = 1;
    }

    fused_tc2_kernel<<<8192, TPB, SMEM>>>(kv_in, q_in, key_w, key_b, value_w, value_b,
                                          query_w, query_b, scale, d1_w, d2_w, d3_w, d3_b,
                                          out);
}